// round 4
// baseline (speedup 1.0000x reference)
#include <cuda_runtime.h>

#define N     8192
#define OBS   64
#define ACT   16
#define ITERS 64

#define ROWS_PER_BLOCK 8          // 8 warps/block, warp-per-row
#define FIRST_ROW (OBS + 1)       // rows 0..64 of intermediate outputs are discarded

// Rows [FIRST_ROW, SPLIT_ROW) are loaded with an L2 evict_last cache-hint
// policy (resident set, ~104.5 MB of the ~126 MB L2); rows >= SPLIT_ROW
// stream with an evict_first policy.
#define SPLIT_ROW 3400

// Ping-pong hidden-state buffers (device globals: no allocation allowed).
__device__ float g_hA[N];
__device__ float g_hB[N];

__device__ __forceinline__ unsigned long long mk_policy_evict_last() {
    unsigned long long pol;
    asm("createpolicy.fractional.L2::evict_last.b64 %0, 1.0;" : "=l"(pol));
    return pol;
}
__device__ __forceinline__ unsigned long long mk_policy_evict_first() {
    unsigned long long pol;
    asm("createpolicy.fractional.L2::evict_first.b64 %0, 1.0;" : "=l"(pol));
    return pol;
}
__device__ __forceinline__ float4 ldg_hint(const float4* p, unsigned long long pol) {
    float4 v;
    asm("ld.global.nc.L2::cache_hint.v4.f32 {%0,%1,%2,%3}, [%4], %5;"
        : "=f"(v.x), "=f"(v.y), "=f"(v.z), "=f"(v.w)
        : "l"(p), "l"(pol));
    return v;
}

__global__ void init_kernel(const float* __restrict__ obs,
                            const float* __restrict__ h0) {
    int i = blockIdx.x * blockDim.x + threadIdx.x;
    if (i >= N) return;
    if (i == 0) {
        g_hA[0] = 1.0f;
        g_hB[0] = 1.0f;
    } else if (i <= OBS) {
        float v = obs[i - 1];
        g_hA[i] = v;
        g_hB[i] = v;
    } else {
        g_hA[i] = h0[i];
    }
}

// One RNN step: hout[row] = tanh(W[row,:] . hin) for row in [FIRST_ROW, N).
__global__ __launch_bounds__(32 * ROWS_PER_BLOCK)
void gemv_tanh_kernel(const float4* __restrict__ W, int srcA) {
    const float4* __restrict__ hin =
        (const float4*)(srcA ? (const float*)g_hA : (const float*)g_hB);
    float* __restrict__ hout = srcA ? g_hB : g_hA;

    const int warp = threadIdx.x >> 5;
    const int lane = threadIdx.x & 31;
    const int row  = FIRST_ROW + blockIdx.x * ROWS_PER_BLOCK + warp;
    if (row >= N) return;

    const float4* __restrict__ wr = W + (size_t)row * (N / 4);

    const unsigned long long pol = (row < SPLIT_ROW) ? mk_policy_evict_last()
                                                     : mk_policy_evict_first();
    float acc = 0.0f;
#pragma unroll 8
    for (int i = 0; i < (N / 4) / 32; ++i) {        // 64 iterations
        float4 w = ldg_hint(&wr[i * 32 + lane], pol);
        float4 h = __ldg(&hin[i * 32 + lane]);
        acc += w.x * h.x + w.y * h.y + w.z * h.z + w.w * h.w;
    }
#pragma unroll
    for (int off = 16; off; off >>= 1)
        acc += __shfl_down_sync(0xffffffffu, acc, off);
    if (lane == 0)
        hout[row] = tanhf(acc);
}

// Final step: only the last ACT rows are needed; write straight to d_out.
__global__ __launch_bounds__(32 * ACT)
void gemv_tail_kernel(const float4* __restrict__ W, int srcA,
                      float* __restrict__ out) {
    const float4* __restrict__ hin =
        (const float4*)(srcA ? (const float*)g_hA : (const float*)g_hB);

    const int warp = threadIdx.x >> 5;   // 0..15
    const int lane = threadIdx.x & 31;
    const int row  = (N - ACT) + warp;

    const float4* __restrict__ wr = W + (size_t)row * (N / 4);
    const unsigned long long pol = mk_policy_evict_first();

    float acc = 0.0f;
#pragma unroll 8
    for (int i = 0; i < (N / 4) / 32; ++i) {
        float4 w = ldg_hint(&wr[i * 32 + lane], pol);
        float4 h = __ldg(&hin[i * 32 + lane]);
        acc += w.x * h.x + w.y * h.y + w.z * h.z + w.w * h.w;
    }
#pragma unroll
    for (int off = 16; off; off >>= 1)
        acc += __shfl_down_sync(0xffffffffu, acc, off);
    if (lane == 0)
        out[warp] = tanhf(acc);
}

extern "C" void kernel_launch(void* const* d_in, const int* in_sizes, int n_in,
                              void* d_out, int out_size) {
    const float* W   = (const float*)d_in[0];  // [N, N] fp32, row-major
    const float* obs = (const float*)d_in[1];  // [OBS]
    const float* h0  = (const float*)d_in[2];  // [N]
    float* out = (float*)d_out;                // [ACT]

    init_kernel<<<(N + 255) / 256, 256>>>(obs, h0);

    const int rows   = N - FIRST_ROW;
    const int blocks = (rows + ROWS_PER_BLOCK - 1) / ROWS_PER_BLOCK;

    int srcA = 1;
    for (int it = 0; it < ITERS - 1; ++it) {                   // 63 full steps
        gemv_tanh_kernel<<<blocks, 32 * ROWS_PER_BLOCK>>>((const float4*)W, srcA);
        srcA ^= 1;
    }
    gemv_tail_kernel<<<1, 32 * ACT>>>((const float4*)W, srcA, out);  // step 64
}

// round 5
// speedup vs baseline: 1.6702x; 1.6702x over previous
#include <cuda_runtime.h>
#include <cuda_fp16.h>

#define N     8192
#define OBS   64
#define ACT   16
#define ITERS 64

#define ROWS_PER_BLOCK 8          // 8 warps/block, warp-per-row
#define FIRST_ROW (OBS + 1)       // rows 0..64 of intermediate outputs are discarded
#define WROWS (N - FIRST_ROW)     // 8127 rows actually needed

// fp16 copy of the needed W rows (127 MB) — device global, no allocation.
__device__ __half g_Wh[(size_t)WROWS * N];

// Ping-pong hidden-state buffers.
__device__ float g_hA[N];
__device__ float g_hB[N];

__global__ void init_kernel(const float* __restrict__ obs,
                            const float* __restrict__ h0) {
    int i = blockIdx.x * blockDim.x + threadIdx.x;
    if (i >= N) return;
    if (i == 0) {
        g_hA[0] = 1.0f;
        g_hB[0] = 1.0f;
    } else if (i <= OBS) {
        float v = obs[i - 1];
        g_hA[i] = v;
        g_hB[i] = v;
    } else {
        g_hA[i] = h0[i];
    }
}

// Convert W rows [FIRST_ROW, N) fp32 -> fp16. Grid-stride, 4 elems/thread/iter.
__global__ __launch_bounds__(256)
void convert_kernel(const float4* __restrict__ Wsrc /* = W + FIRST_ROW*N */) {
    const size_t total4 = (size_t)WROWS * (N / 4);
    uint2* __restrict__ dst = (uint2*)g_Wh;        // 4 halves per uint2
    size_t stride = (size_t)gridDim.x * blockDim.x;
    for (size_t i = blockIdx.x * (size_t)blockDim.x + threadIdx.x;
         i < total4; i += stride) {
        float4 v = Wsrc[i];
        __half2 lo = __floats2half2_rn(v.x, v.y);
        __half2 hi = __floats2half2_rn(v.z, v.w);
        uint2 o;
        o.x = *(unsigned*)&lo;
        o.y = *(unsigned*)&hi;
        dst[i] = o;
    }
}

// One RNN step on fp16 weights: hout[row] = tanh(Wrow . hin), rows [FIRST_ROW,N).
__global__ __launch_bounds__(32 * ROWS_PER_BLOCK)
void gemv_tanh_h_kernel(int srcA) {
    const float4* __restrict__ hin =
        (const float4*)(srcA ? (const float*)g_hA : (const float*)g_hB);
    float* __restrict__ hout = srcA ? g_hB : g_hA;

    const int warp = threadIdx.x >> 5;
    const int lane = threadIdx.x & 31;
    const int r    = blockIdx.x * ROWS_PER_BLOCK + warp;   // 0..WROWS-1
    if (r >= WROWS) return;

    const uint4* __restrict__ wr = (const uint4*)(g_Wh + (size_t)r * N);

    float acc = 0.0f;
#pragma unroll 8
    for (int i = 0; i < N / (32 * 8); ++i) {               // 32 iterations
        const int j = i * 32 + lane;                       // 8 halves per lane
        uint4 w = wr[j];
        float4 h0 = __ldg(&hin[2 * j + 0]);
        float4 h1 = __ldg(&hin[2 * j + 1]);
        float2 f0 = __half22float2(*(const __half2*)&w.x);
        float2 f1 = __half22float2(*(const __half2*)&w.y);
        float2 f2 = __half22float2(*(const __half2*)&w.z);
        float2 f3 = __half22float2(*(const __half2*)&w.w);
        acc += f0.x * h0.x + f0.y * h0.y + f1.x * h0.z + f1.y * h0.w
             + f2.x * h1.x + f2.y * h1.y + f3.x * h1.z + f3.y * h1.w;
    }
#pragma unroll
    for (int off = 16; off; off >>= 1)
        acc += __shfl_down_sync(0xffffffffu, acc, off);
    if (lane == 0)
        hout[FIRST_ROW + r] = tanhf(acc);
}

// Final step: only last ACT rows, straight to d_out.
__global__ __launch_bounds__(32 * ACT)
void gemv_tail_h_kernel(int srcA, float* __restrict__ out) {
    const float4* __restrict__ hin =
        (const float4*)(srcA ? (const float*)g_hA : (const float*)g_hB);

    const int warp = threadIdx.x >> 5;   // 0..15
    const int lane = threadIdx.x & 31;
    const int r    = (WROWS - ACT) + warp;

    const uint4* __restrict__ wr = (const uint4*)(g_Wh + (size_t)r * N);

    float acc = 0.0f;
#pragma unroll 8
    for (int i = 0; i < N / (32 * 8); ++i) {
        const int j = i * 32 + lane;
        uint4 w = wr[j];
        float4 h0 = __ldg(&hin[2 * j + 0]);
        float4 h1 = __ldg(&hin[2 * j + 1]);
        float2 f0 = __half22float2(*(const __half2*)&w.x);
        float2 f1 = __half22float2(*(const __half2*)&w.y);
        float2 f2 = __half22float2(*(const __half2*)&w.z);
        float2 f3 = __half22float2(*(const __half2*)&w.w);
        acc += f0.x * h0.x + f0.y * h0.y + f1.x * h0.z + f1.y * h0.w
             + f2.x * h1.x + f2.y * h1.y + f3.x * h1.z + f3.y * h1.w;
    }
#pragma unroll
    for (int off = 16; off; off >>= 1)
        acc += __shfl_down_sync(0xffffffffu, acc, off);
    if (lane == 0)
        out[warp] = tanhf(acc);
}

extern "C" void kernel_launch(void* const* d_in, const int* in_sizes, int n_in,
                              void* d_out, int out_size) {
    const float* W   = (const float*)d_in[0];  // [N, N] fp32, row-major
    const float* obs = (const float*)d_in[1];  // [OBS]
    const float* h0  = (const float*)d_in[2];  // [N]
    float* out = (float*)d_out;                // [ACT]

    init_kernel<<<(N + 255) / 256, 256>>>(obs, h0);
    convert_kernel<<<148 * 16, 256>>>((const float4*)(W + (size_t)FIRST_ROW * N));

    const int blocks = (WROWS + ROWS_PER_BLOCK - 1) / ROWS_PER_BLOCK;

    int srcA = 1;
    for (int it = 0; it < ITERS - 1; ++it) {                 // 63 full steps
        gemv_tanh_h_kernel<<<blocks, 32 * ROWS_PER_BLOCK>>>(srcA);
        srcA ^= 1;
    }
    gemv_tail_h_kernel<<<1, 32 * ACT>>>(srcA, out);          // step 64
}